// round 3
// baseline (speedup 1.0000x reference)
#include <cuda_runtime.h>

// 2x FIR upsample, depthwise separable [1,3,3,1]/4 per axis (factor=2 gain).
//   out[2i]   = 0.25*x[i-1] + 0.75*x[i]
//   out[2i+1] = 0.75*x[i]   + 0.25*x[i+1]
// Input (8,128,128,128) f32 -> Output (8,128,256,256) f32.
//
// No shared memory: one warp owns a full-width (128-col) strip of 8 input rows.
// Lane l holds cols 4l..4l+3 (one LDG.128 per row); horizontal halo via shfl.

#define H_IN 128
#define W_IN 128
#define W_OUT 256
#define ROWS_PER_WARP 8

// Horizontal 2x upsample of one row-vector (4 cols/lane -> 8 out cols/lane).
__device__ __forceinline__ void hup(float4 v, int lane, float h[8]) {
    float left  = __shfl_up_sync(0xFFFFFFFFu, v.w, 1);
    float right = __shfl_down_sync(0xFFFFFFFFu, v.x, 1);
    if (lane == 0)  left  = 0.f;   // x[-1] = 0 (zero pad)
    if (lane == 31) right = 0.f;   // x[W]  = 0
    float c0 = left, c1 = v.x, c2 = v.y, c3 = v.z, c4 = v.w, c5 = right;
    h[0] = 0.25f * c0 + 0.75f * c1;
    h[1] = 0.75f * c1 + 0.25f * c2;
    h[2] = 0.25f * c1 + 0.75f * c2;
    h[3] = 0.75f * c2 + 0.25f * c3;
    h[4] = 0.25f * c2 + 0.75f * c3;
    h[5] = 0.75f * c3 + 0.25f * c4;
    h[6] = 0.25f * c3 + 0.75f * c4;
    h[7] = 0.75f * c4 + 0.25f * c5;
}

__global__ __launch_bounds__(256)
void upsample2x_fir_kernel(const float* __restrict__ x, float* __restrict__ out) {
    const int warp = threadIdx.x >> 5;
    const int lane = threadIdx.x & 31;

    const int strip = blockIdx.x * 8 + warp;                // 0..15
    const int chan  = blockIdx.z * gridDim.y + blockIdx.y;  // b*C + c
    const float* xp = x   + (size_t)chan * (H_IN * W_IN);
    float*       op = out + (size_t)chan * (2 * H_IN * W_OUT);

    const int r0 = strip * ROWS_PER_WARP;
    const int jg = lane * 4;                                // global col base

    // Front-batched loads: rows r0-1 .. r0+8 (10 rows), one LDG.128 each.
    float4 v[ROWS_PER_WARP + 2];
    #pragma unroll
    for (int i = 0; i < ROWS_PER_WARP + 2; i++) {
        const int gr = r0 - 1 + i;
        if (gr >= 0 && gr < H_IN)
            v[i] = *(const float4*)(xp + (size_t)gr * W_IN + jg);
        else
            v[i] = make_float4(0.f, 0.f, 0.f, 0.f);
    }

    // Streaming vertical blend over horizontally-upsampled rows.
    float hprev[8], hcur[8], hnext[8];
    hup(v[0], lane, hprev);
    hup(v[1], lane, hcur);

    #pragma unroll
    for (int i = 0; i < ROWS_PER_WARP; i++) {
        hup(v[i + 2], lane, hnext);

        float ev[8], od[8];
        #pragma unroll
        for (int k = 0; k < 8; k++) {
            ev[k] = 0.25f * hprev[k] + 0.75f * hcur[k];   // out row 2*(r0+i)
            od[k] = 0.75f * hcur[k]  + 0.25f * hnext[k];  // out row 2*(r0+i)+1
        }

        float* q0 = op + (size_t)(2 * (r0 + i)) * W_OUT + 2 * jg;
        float* q1 = q0 + W_OUT;
        *(float4*)(q0    ) = make_float4(ev[0], ev[1], ev[2], ev[3]);
        *(float4*)(q0 + 4) = make_float4(ev[4], ev[5], ev[6], ev[7]);
        *(float4*)(q1    ) = make_float4(od[0], od[1], od[2], od[3]);
        *(float4*)(q1 + 4) = make_float4(od[4], od[5], od[6], od[7]);

        #pragma unroll
        for (int k = 0; k < 8; k++) { hprev[k] = hcur[k]; hcur[k] = hnext[k]; }
    }
}

extern "C" void kernel_launch(void* const* d_in, const int* in_sizes, int n_in,
                              void* d_out, int out_size) {
    const float* x = (const float*)d_in[0];
    float* out = (float*)d_out;
    // 8 warps/block, each warp = one 8-row strip; 16 strips/channel -> grid.x=2
    dim3 grid(2, 128, 8);   // (strip blocks, C, B)
    upsample2x_fir_kernel<<<grid, 256>>>(x, out);
}

// round 6
// speedup vs baseline: 1.2931x; 1.2931x over previous
#include <cuda_runtime.h>

// 2x FIR upsample, depthwise separable [1,3,3,1]/4 per axis (factor=2 gain).
//   out[2i]   = 0.25*x[i-1] + 0.75*x[i]
//   out[2i+1] = 0.75*x[i]   + 0.25*x[i+1]
// Input (8,128,128,128) f32 -> Output (8,128,256,256) f32.
//
// Vertical-first: blend raw rows in float4 (no horizontal halo needed in smem),
// then horizontal upsample in registers with warp shuffles.

#define H_IN 128
#define W_IN 128
#define W_OUT 256
#define RPB 16                   // input rows per block
#define TROWS (RPB + 2)          // raw rows staged: r0-1 .. r0+16
#define TSF 128                  // tile row stride in floats (aligned, conflict-free)

__device__ __forceinline__ float4 blend(float wa, float4 a, float wb, float4 b) {
    return make_float4(wa*a.x + wb*b.x, wa*a.y + wb*b.y,
                       wa*a.z + wb*b.z, wa*a.w + wb*b.w);
}

// Horizontal 2x upsample of one (already vertically blended) row vector.
// Lane l holds cols 4l..4l+3; halo via shfl (zero at edges since W=128=32*4).
__device__ __forceinline__ void hup(float4 v, int lane, float4& lo, float4& hi) {
    float left  = __shfl_up_sync(0xFFFFFFFFu, v.w, 1);
    float right = __shfl_down_sync(0xFFFFFFFFu, v.x, 1);
    if (lane == 0)  left  = 0.f;
    if (lane == 31) right = 0.f;
    lo.x = 0.25f * left + 0.75f * v.x;
    lo.y = 0.75f * v.x  + 0.25f * v.y;
    lo.z = 0.25f * v.x  + 0.75f * v.y;
    lo.w = 0.75f * v.y  + 0.25f * v.z;
    hi.x = 0.25f * v.y  + 0.75f * v.z;
    hi.y = 0.75f * v.z  + 0.25f * v.w;
    hi.z = 0.25f * v.z  + 0.75f * v.w;
    hi.w = 0.75f * v.w  + 0.25f * right;
}

__global__ __launch_bounds__(256)
void upsample2x_fir_kernel(const float* __restrict__ x, float* __restrict__ out) {
    __shared__ __align__(16) float tile[TROWS * TSF];

    const int rb   = blockIdx.x;                             // 0..7
    const int chan = blockIdx.z * gridDim.y + blockIdx.y;    // b*C + c
    const float* xp = x   + (size_t)chan * (H_IN * W_IN);
    float*       op = out + (size_t)chan * (2 * H_IN * W_OUT);

    const int r0  = rb * RPB;
    const int tid = threadIdx.x;

    // ---- cooperative staging: raw rows r0-1 .. r0+16, zero rows out of range ----
    #pragma unroll
    for (int idx = tid; idx < TROWS * 32; idx += 256) {
        const int sy = idx >> 5;         // tile row
        const int f4 = idx & 31;         // float4 within row
        const int gr = r0 - 1 + sy;
        float4 v = make_float4(0.f, 0.f, 0.f, 0.f);
        if (gr >= 0 && gr < H_IN)
            v = *(const float4*)(xp + (size_t)gr * W_IN + f4 * 4);
        *(float4*)&tile[sy * TSF + f4 * 4] = v;
    }
    __syncthreads();

    // ---- compute: thread (lane, ty) handles input rows r0+2ty, r0+2ty+1 ----
    const int lane = tid & 31;
    const int ty   = tid >> 5;           // 0..7
    const int jc   = lane * 4;           // col base

    // tile row s holds raw row r0-1+s; input row (r0+li) is tile row li+1
    const float4 m0 = *(const float4*)&tile[(2*ty    ) * TSF + jc];  // row -1
    const float4 m1 = *(const float4*)&tile[(2*ty + 1) * TSF + jc];  // row  0
    const float4 m2 = *(const float4*)&tile[(2*ty + 2) * TSF + jc];  // row +1
    const float4 m3 = *(const float4*)&tile[(2*ty + 3) * TSF + jc];  // row +2

    // vertical blends: 4 output rows
    const float4 e0 = blend(0.25f, m0, 0.75f, m1);   // out row 2*(r0+2ty)
    const float4 o0 = blend(0.75f, m1, 0.25f, m2);   // out row 2*(r0+2ty)+1
    const float4 e1 = blend(0.25f, m1, 0.75f, m2);   // out row 2*(r0+2ty)+2
    const float4 o1 = blend(0.75f, m2, 0.25f, m3);   // out row 2*(r0+2ty)+3

    const int orow = 2 * (r0 + 2 * ty);
    float* q = op + (size_t)orow * W_OUT + 2 * jc;

    float4 lo, hi;
    hup(e0, lane, lo, hi);
    *(float4*)(q)                 = lo;  *(float4*)(q + 4)             = hi;
    hup(o0, lane, lo, hi);
    *(float4*)(q + W_OUT)         = lo;  *(float4*)(q + W_OUT + 4)     = hi;
    hup(e1, lane, lo, hi);
    *(float4*)(q + 2 * W_OUT)     = lo;  *(float4*)(q + 2 * W_OUT + 4) = hi;
    hup(o1, lane, lo, hi);
    *(float4*)(q + 3 * W_OUT)     = lo;  *(float4*)(q + 3 * W_OUT + 4) = hi;
}

extern "C" void kernel_launch(void* const* d_in, const int* in_sizes, int n_in,
                              void* d_out, int out_size) {
    const float* x = (const float*)d_in[0];
    float* out = (float*)d_out;
    dim3 grid(H_IN / RPB, 128, 8);   // (row blocks, C, B)
    upsample2x_fir_kernel<<<grid, 256>>>(x, out);
}